// round 1
// baseline (speedup 1.0000x reference)
#include <cuda_runtime.h>
#include <math.h>

#define SEQ  2048
#define BAT  2
#define DM   1024
#define NH   16
#define HDM  64
#define DFF  4096
#define ROWS (SEQ*BAT)   // 4096

// ---------------- scratch (static device globals; no allocation) ----------------
__device__ float g_xln[ROWS * DM];        // LN output (reused for LN1 and LN2)
__device__ float g_qkv[ROWS * 3 * DM];    // QKV projection [S,B,3D]
__device__ float g_q[BAT * NH * SEQ * HDM];
__device__ float g_k[BAT * NH * SEQ * HDM];
__device__ float g_v[BAT * NH * SEQ * HDM];
__device__ float g_att[ROWS * DM];        // attention out in [S,B,D]
__device__ float g_x[ROWS * DM];          // residual-1 result
__device__ float g_h1[ROWS * DFF];        // FFN hidden

// ---------------- LayerNorm: one block per row of 1024 ----------------
__global__ __launch_bounds__(256) void ln_kernel(
    const float* __restrict__ x, const float* __restrict__ g,
    const float* __restrict__ b, float* __restrict__ y)
{
    int row = blockIdx.x;
    int t = threadIdx.x;
    const float4* xr = (const float4*)(x + (size_t)row * DM);
    float4 v = xr[t];
    float s  = v.x + v.y + v.z + v.w;
    float ss = v.x*v.x + v.y*v.y + v.z*v.z + v.w*v.w;
    #pragma unroll
    for (int o = 16; o > 0; o >>= 1) {
        s  += __shfl_xor_sync(0xffffffffu, s,  o);
        ss += __shfl_xor_sync(0xffffffffu, ss, o);
    }
    __shared__ float red[18];
    if ((t & 31) == 0) { red[t >> 5] = s; red[(t >> 5) + 8] = ss; }
    __syncthreads();
    if (t == 0) {
        float S_ = 0.f, SS = 0.f;
        #pragma unroll
        for (int i = 0; i < 8; i++) { S_ += red[i]; SS += red[i + 8]; }
        float mu  = S_ * (1.f / DM);
        float var = SS * (1.f / DM) - mu * mu;
        red[16] = mu;
        red[17] = rsqrtf(var + 1e-5f);
    }
    __syncthreads();
    float mu = red[16], inv = red[17];
    float4 gg = ((const float4*)g)[t];
    float4 bb = ((const float4*)b)[t];
    float4 o;
    o.x = (v.x - mu) * inv * gg.x + bb.x;
    o.y = (v.y - mu) * inv * gg.y + bb.y;
    o.z = (v.z - mu) * inv * gg.z + bb.z;
    o.w = (v.w - mu) * inv * gg.w + bb.w;
    ((float4*)(y + (size_t)row * DM))[t] = o;
}

// ---------------- GEMM: C[M,N] = A[M,K] @ W[N,K]^T (+bias, +res, relu) ----------------
// 128x128 block tile, K-tile 8, 256 threads, 8x8 register tile split 2x(4+4).
template<bool RELU, bool RES>
__global__ __launch_bounds__(256) void gemm_nt(
    const float* __restrict__ A, const float* __restrict__ W,
    const float* __restrict__ bias, const float* __restrict__ res,
    float* __restrict__ C, int M, int N, int K)
{
    __shared__ float As[8][128];
    __shared__ float Bs[8][128];
    int tid = threadIdx.x;
    int tx = tid & 15, ty = tid >> 4;
    int m0 = blockIdx.y << 7, n0 = blockIdx.x << 7;
    int lr = tid >> 1;
    int lc = (tid & 1) << 2;
    const float* Ap = A + (size_t)(m0 + lr) * K + lc;
    const float* Wp = W + (size_t)(n0 + lr) * K + lc;

    float acc[8][8];
    #pragma unroll
    for (int i = 0; i < 8; i++)
        #pragma unroll
        for (int j = 0; j < 8; j++) acc[i][j] = 0.f;

    for (int k0 = 0; k0 < K; k0 += 8) {
        float4 av = *(const float4*)(Ap + k0);
        float4 wv = *(const float4*)(Wp + k0);
        __syncthreads();
        As[lc][lr] = av.x; As[lc + 1][lr] = av.y; As[lc + 2][lr] = av.z; As[lc + 3][lr] = av.w;
        Bs[lc][lr] = wv.x; Bs[lc + 1][lr] = wv.y; Bs[lc + 2][lr] = wv.z; Bs[lc + 3][lr] = wv.w;
        __syncthreads();
        #pragma unroll
        for (int kk = 0; kk < 8; kk++) {
            float a[8], b[8];
            *(float4*)(a)     = *(const float4*)&As[kk][ty << 2];
            *(float4*)(a + 4) = *(const float4*)&As[kk][(ty << 2) + 64];
            *(float4*)(b)     = *(const float4*)&Bs[kk][tx << 2];
            *(float4*)(b + 4) = *(const float4*)&Bs[kk][(tx << 2) + 64];
            #pragma unroll
            for (int i = 0; i < 8; i++)
                #pragma unroll
                for (int j = 0; j < 8; j++)
                    acc[i][j] += a[i] * b[j];
        }
    }

    #pragma unroll
    for (int i = 0; i < 8; i++) {
        int r = m0 + (ty << 2) + (i < 4 ? i : 60 + i);
        #pragma unroll
        for (int jh = 0; jh < 2; jh++) {
            int c = n0 + (tx << 2) + jh * 64;
            float4 o;
            o.x = acc[i][jh * 4 + 0];
            o.y = acc[i][jh * 4 + 1];
            o.z = acc[i][jh * 4 + 2];
            o.w = acc[i][jh * 4 + 3];
            float4 bv = *(const float4*)(bias + c);
            o.x += bv.x; o.y += bv.y; o.z += bv.z; o.w += bv.w;
            if (RES) {
                float4 rv = *(const float4*)(res + (size_t)r * N + c);
                o.x += rv.x; o.y += rv.y; o.z += rv.z; o.w += rv.w;
            }
            if (RELU) {
                o.x = fmaxf(o.x, 0.f); o.y = fmaxf(o.y, 0.f);
                o.z = fmaxf(o.z, 0.f); o.w = fmaxf(o.w, 0.f);
            }
            *(float4*)(C + (size_t)r * N + c) = o;
        }
    }
}

// ---------------- RoPE + layout [S,B,3D] -> Q/K/V [B*H, S, HD] ----------------
__global__ __launch_bounds__(256) void rope_kernel(
    const float* __restrict__ qkv, const float* __restrict__ sn,
    const float* __restrict__ cs,
    float* __restrict__ Q, float* __restrict__ K, float* __restrict__ V)
{
    int idx = blockIdx.x * 256 + threadIdx.x;   // 2^21 total
    int p = idx & 31;
    int s = (idx >> 5) & 2047;
    int h = (idx >> 16) & 15;
    int b = idx >> 20;
    size_t rb = ((size_t)s * BAT + b) * (3 * DM) + h * HDM + 2 * p;
    float2 q = *(const float2*)(qkv + rb);
    float2 k = *(const float2*)(qkv + rb + DM);
    float2 v = *(const float2*)(qkv + rb + 2 * DM);
    float sv = sn[s * 32 + p], cv = cs[s * 32 + p];
    float2 qo = make_float2(q.x * cv - q.y * sv, q.y * cv + q.x * sv);
    float2 ko = make_float2(k.x * cv - k.y * sv, k.y * cv + k.x * sv);
    size_t ob = ((size_t)(b * NH + h) * SEQ + s) * HDM + 2 * p;
    *(float2*)(Q + ob) = qo;
    *(float2*)(K + ob) = ko;
    *(float2*)(V + ob) = v;
}

// ---------------- Flash attention (fp32), 64-query tiles, causal ----------------
// grid (S/64, B*H), 256 threads. Writes output directly in [S,B,D] layout.
__global__ __launch_bounds__(256) void attn_kernel(
    const float* __restrict__ Q, const float* __restrict__ K,
    const float* __restrict__ V, float* __restrict__ Out)
{
    extern __shared__ float smem[];
    float* Qt = smem;              // [64][64]  d-major: Qt[d*64+q]
    float* Kt = smem + 4096;       // [64][68]  d-major (reused as Pt[k][68] rows)
    float* Vs = Kt + 64 * 68;      // [64][64]  k-major
    int tid = threadIdx.x;
    int tx = tid & 15, ty = tid >> 4;
    int qb = blockIdx.x, bh = blockIdx.y;
    int b = bh >> 4, h = bh & 15;

    const float* Qp = Q + ((size_t)bh * SEQ + qb * 64) * HDM;
    #pragma unroll
    for (int i = 0; i < 4; i++) {
        int lin = tid + i * 256;
        int r = lin >> 4, c4 = (lin & 15) << 2;
        float4 v = *(const float4*)(Qp + r * 64 + c4);
        Qt[(c4 + 0) * 64 + r] = v.x;
        Qt[(c4 + 1) * 64 + r] = v.y;
        Qt[(c4 + 2) * 64 + r] = v.z;
        Qt[(c4 + 3) * 64 + r] = v.w;
    }

    float o[4][4];
    float m_i[4], l_i[4];
    #pragma unroll
    for (int qi = 0; qi < 4; qi++) {
        m_i[qi] = -1e30f; l_i[qi] = 0.f;
        #pragma unroll
        for (int di = 0; di < 4; di++) o[qi][di] = 0.f;
    }

    for (int kb = 0; kb <= qb; kb++) {
        const float* Kp = K + ((size_t)bh * SEQ + kb * 64) * HDM;
        const float* Vp = V + ((size_t)bh * SEQ + kb * 64) * HDM;
        __syncthreads();
        #pragma unroll
        for (int i = 0; i < 4; i++) {
            int lin = tid + i * 256;
            int r = lin >> 4, c4 = (lin & 15) << 2;
            float4 kv = *(const float4*)(Kp + r * 64 + c4);
            Kt[(c4 + 0) * 68 + r] = kv.x;
            Kt[(c4 + 1) * 68 + r] = kv.y;
            Kt[(c4 + 2) * 68 + r] = kv.z;
            Kt[(c4 + 3) * 68 + r] = kv.w;
            float4 vv = *(const float4*)(Vp + r * 64 + c4);
            *(float4*)(Vs + r * 64 + c4) = vv;
        }
        __syncthreads();

        float s[4][4];
        #pragma unroll
        for (int qi = 0; qi < 4; qi++)
            #pragma unroll
            for (int ki = 0; ki < 4; ki++) s[qi][ki] = 0.f;

        #pragma unroll 8
        for (int d = 0; d < 64; d++) {
            float aq[4], bk[4];
            *(float4*)aq = *(const float4*)(Qt + d * 64 + (ty << 2));
            *(float4*)bk = *(const float4*)(Kt + d * 68 + (tx << 2));
            #pragma unroll
            for (int qi = 0; qi < 4; qi++)
                #pragma unroll
                for (int ki = 0; ki < 4; ki++)
                    s[qi][ki] += aq[qi] * bk[ki];
        }

        bool diag = (kb == qb);
        #pragma unroll
        for (int qi = 0; qi < 4; qi++)
            #pragma unroll
            for (int ki = 0; ki < 4; ki++) {
                s[qi][ki] *= 0.125f;  // 1/sqrt(64)
                if (diag && ((tx << 2) + ki) > ((ty << 2) + qi)) s[qi][ki] = -1e30f;
            }

        // online softmax per q-row (row split across 16 tx lanes)
        #pragma unroll
        for (int qi = 0; qi < 4; qi++) {
            float mx = fmaxf(fmaxf(s[qi][0], s[qi][1]), fmaxf(s[qi][2], s[qi][3]));
            mx = fmaxf(mx, __shfl_xor_sync(0xffffffffu, mx, 1));
            mx = fmaxf(mx, __shfl_xor_sync(0xffffffffu, mx, 2));
            mx = fmaxf(mx, __shfl_xor_sync(0xffffffffu, mx, 4));
            mx = fmaxf(mx, __shfl_xor_sync(0xffffffffu, mx, 8));
            float mn = fmaxf(m_i[qi], mx);
            float al = __expf(m_i[qi] - mn);
            float rs = 0.f;
            #pragma unroll
            for (int ki = 0; ki < 4; ki++) {
                s[qi][ki] = __expf(s[qi][ki] - mn);
                rs += s[qi][ki];
            }
            rs += __shfl_xor_sync(0xffffffffu, rs, 1);
            rs += __shfl_xor_sync(0xffffffffu, rs, 2);
            rs += __shfl_xor_sync(0xffffffffu, rs, 4);
            rs += __shfl_xor_sync(0xffffffffu, rs, 8);
            l_i[qi] = l_i[qi] * al + rs;
            m_i[qi] = mn;
            #pragma unroll
            for (int di = 0; di < 4; di++) o[qi][di] *= al;
        }

        __syncthreads();
        // write P transposed into Kt region: Pt[k][q], row stride 68
        #pragma unroll
        for (int ki = 0; ki < 4; ki++) {
            *(float4*)(Kt + ((tx << 2) + ki) * 68 + (ty << 2)) =
                make_float4(s[0][ki], s[1][ki], s[2][ki], s[3][ki]);
        }
        __syncthreads();

        #pragma unroll 8
        for (int k = 0; k < 64; k++) {
            float ap[4], bv[4];
            *(float4*)ap = *(const float4*)(Kt + k * 68 + (ty << 2));
            *(float4*)bv = *(const float4*)(Vs + k * 64 + (tx << 2));
            #pragma unroll
            for (int qi = 0; qi < 4; qi++)
                #pragma unroll
                for (int di = 0; di < 4; di++)
                    o[qi][di] += ap[qi] * bv[di];
        }
    }

    #pragma unroll
    for (int qi = 0; qi < 4; qi++) {
        float inv = 1.f / l_i[qi];
        int qg = qb * 64 + (ty << 2) + qi;
        float4 ov = make_float4(o[qi][0] * inv, o[qi][1] * inv,
                                o[qi][2] * inv, o[qi][3] * inv);
        *(float4*)(Out + ((size_t)qg * BAT + b) * DM + h * HDM + (tx << 2)) = ov;
    }
}

// ---------------- launcher ----------------
extern "C" void kernel_launch(void* const* d_in, const int* in_sizes, int n_in,
                              void* d_out, int out_size)
{
    const float* src  = (const float*)d_in[0];
    const float* sn   = (const float*)d_in[1];
    const float* cs   = (const float*)d_in[2];
    const float* wqkv = (const float*)d_in[3];
    const float* bqkv = (const float*)d_in[4];
    const float* wo   = (const float*)d_in[5];
    const float* bo   = (const float*)d_in[6];
    const float* g1   = (const float*)d_in[7];
    const float* be1  = (const float*)d_in[8];
    const float* g2   = (const float*)d_in[9];
    const float* be2  = (const float*)d_in[10];
    const float* w1   = (const float*)d_in[11];
    const float* bb1  = (const float*)d_in[12];
    const float* w2   = (const float*)d_in[13];
    const float* bb2  = (const float*)d_in[14];
    float* out = (float*)d_out;

    float *xln, *qkv, *q, *k, *v, *att, *x, *h1;
    cudaGetSymbolAddress((void**)&xln, g_xln);
    cudaGetSymbolAddress((void**)&qkv, g_qkv);
    cudaGetSymbolAddress((void**)&q,   g_q);
    cudaGetSymbolAddress((void**)&k,   g_k);
    cudaGetSymbolAddress((void**)&v,   g_v);
    cudaGetSymbolAddress((void**)&att, g_att);
    cudaGetSymbolAddress((void**)&x,   g_x);
    cudaGetSymbolAddress((void**)&h1,  g_h1);

    const int ATTN_SMEM = (4096 + 64 * 68 + 4096) * 4;  // 50176 bytes
    cudaFuncSetAttribute(attn_kernel, cudaFuncAttributeMaxDynamicSharedMemorySize, ATTN_SMEM);

    // 1. LN1
    ln_kernel<<<ROWS, 256>>>(src, g1, be1, xln);
    // 2. QKV projection [4096,3072] = xln @ wqkv^T
    gemm_nt<false, false><<<dim3(3 * DM / 128, ROWS / 128), 256>>>(
        xln, wqkv, bqkv, nullptr, qkv, ROWS, 3 * DM, DM);
    // 3. RoPE + transpose
    rope_kernel<<<(BAT * NH * SEQ * 32) / 256, 256>>>(qkv, sn, cs, q, k, v);
    // 4. Causal flash attention -> att in [S,B,D]
    attn_kernel<<<dim3(SEQ / 64, BAT * NH), 256, ATTN_SMEM>>>(q, k, v, att);
    // 5. out-proj + residual: x = src + att @ wo^T + bo
    gemm_nt<false, true><<<dim3(DM / 128, ROWS / 128), 256>>>(
        att, wo, bo, src, x, ROWS, DM, DM);
    // 6. LN2
    ln_kernel<<<ROWS, 256>>>(x, g2, be2, xln);
    // 7. FFN up + ReLU
    gemm_nt<true, false><<<dim3(DFF / 128, ROWS / 128), 256>>>(
        xln, w1, bb1, nullptr, h1, ROWS, DFF, DM);
    // 8. FFN down + residual -> out
    gemm_nt<false, true><<<dim3(DM / 128, ROWS / 128), 256>>>(
        h1, w2, bb2, x, out, ROWS, DM, DFF);
}

// round 2
// speedup vs baseline: 2.0751x; 2.0751x over previous
#include <cuda_runtime.h>
#include <math.h>
#include <stdint.h>

#define SEQ  2048
#define BAT  2
#define DM   1024
#define NH   16
#define HDM  64
#define DFF  4096
#define ROWS (SEQ*BAT)   // 4096

// ---------------- scratch (static device globals; no allocation) ----------------
__device__ float g_xln[ROWS * DM];
__device__ float g_qkv[ROWS * 3 * DM];
__device__ float g_q[BAT * NH * SEQ * HDM];
__device__ float g_k[BAT * NH * SEQ * HDM];
__device__ float g_v[BAT * NH * SEQ * HDM];
__device__ float g_att[ROWS * DM];
__device__ float g_x[ROWS * DM];
__device__ float g_h1[ROWS * DFF];

// ---------------- LayerNorm ----------------
__global__ __launch_bounds__(256) void ln_kernel(
    const float* __restrict__ x, const float* __restrict__ g,
    const float* __restrict__ b, float* __restrict__ y)
{
    int row = blockIdx.x;
    int t = threadIdx.x;
    const float4* xr = (const float4*)(x + (size_t)row * DM);
    float4 v = xr[t];
    float s  = v.x + v.y + v.z + v.w;
    float ss = v.x*v.x + v.y*v.y + v.z*v.z + v.w*v.w;
    #pragma unroll
    for (int o = 16; o > 0; o >>= 1) {
        s  += __shfl_xor_sync(0xffffffffu, s,  o);
        ss += __shfl_xor_sync(0xffffffffu, ss, o);
    }
    __shared__ float red[18];
    if ((t & 31) == 0) { red[t >> 5] = s; red[(t >> 5) + 8] = ss; }
    __syncthreads();
    if (t == 0) {
        float S_ = 0.f, SS = 0.f;
        #pragma unroll
        for (int i = 0; i < 8; i++) { S_ += red[i]; SS += red[i + 8]; }
        float mu  = S_ * (1.f / DM);
        float var = SS * (1.f / DM) - mu * mu;
        red[16] = mu;
        red[17] = rsqrtf(var + 1e-5f);
    }
    __syncthreads();
    float mu = red[16], inv = red[17];
    float4 gg = ((const float4*)g)[t];
    float4 bb = ((const float4*)b)[t];
    float4 o;
    o.x = (v.x - mu) * inv * gg.x + bb.x;
    o.y = (v.y - mu) * inv * gg.y + bb.y;
    o.z = (v.z - mu) * inv * gg.z + bb.z;
    o.w = (v.w - mu) * inv * gg.w + bb.w;
    ((float4*)(y + (size_t)row * DM))[t] = o;
}

// ---------------- tf32 tensor-core GEMM: C[M,N] = A[M,K] @ W[N,K]^T ----------------
// 128x128 block tile, BK=16, 256 threads = 8 warps (2m x 4n), warp tile 64x32.
// mma.sync.m16n8k8 tf32, cp.async double-buffered smem (stride 20 pad, conflict-free).

__device__ __forceinline__ uint32_t f2tf32(float f) {
    uint32_t u;
    asm("cvt.rna.tf32.f32 %0, %1;" : "=r"(u) : "f"(f));
    return u;
}

#define CPA16(dst, src) \
    asm volatile("cp.async.cg.shared.global [%0], [%1], 16;\n" :: "r"(dst), "l"(src))

template<bool RELU, bool RES>
__global__ __launch_bounds__(256) void gemm_tc(
    const float* __restrict__ A, const float* __restrict__ W,
    const float* __restrict__ bias, const float* __restrict__ res,
    float* __restrict__ C, int M, int N, int K)
{
    const int LDS_ = 20;
    __shared__ float As[2][128 * 20];
    __shared__ float Bs[2][128 * 20];
    int tid = threadIdx.x;
    int warp = tid >> 5, lane = tid & 31;
    int wm = warp >> 2, wn = warp & 3;
    int grp = lane >> 2, tig = lane & 3;
    int m0 = blockIdx.y << 7, n0 = blockIdx.x << 7;

    // gmem->smem: each thread moves 2 float4 per operand per stage
    int lrow = tid >> 2;          // 0..63
    int lcol = (tid & 3) << 2;    // 0,4,8,12
    const float* Ag = A + (size_t)(m0 + lrow) * K + lcol;
    const float* Wg = W + (size_t)(n0 + lrow) * K + lcol;
    uint32_t sA = (uint32_t)__cvta_generic_to_shared(&As[0][0]);
    uint32_t sB = (uint32_t)__cvta_generic_to_shared(&Bs[0][0]);
    uint32_t doff = (uint32_t)(lrow * LDS_ + lcol) * 4u;
    const uint32_t stageB = 128u * LDS_ * 4u;
    const uint32_t halfB  = 64u * LDS_ * 4u;

    float acc[4][4][4];
    #pragma unroll
    for (int mt = 0; mt < 4; mt++)
        #pragma unroll
        for (int nt = 0; nt < 4; nt++)
            #pragma unroll
            for (int i = 0; i < 4; i++) acc[mt][nt][i] = 0.f;

    int KT = K >> 4;

    // prologue: stage 0
    {
        uint32_t ad = sA + doff, bd = sB + doff;
        CPA16(ad, Ag);
        CPA16(ad + halfB, Ag + (size_t)64 * K);
        CPA16(bd, Wg);
        CPA16(bd + halfB, Wg + (size_t)64 * K);
        asm volatile("cp.async.commit_group;\n");
    }

    for (int kt = 0; kt < KT; kt++) {
        if (kt + 1 < KT) {
            int k0 = (kt + 1) << 4;
            uint32_t st = ((kt + 1) & 1) * stageB;
            uint32_t ad = sA + st + doff, bd = sB + st + doff;
            CPA16(ad, Ag + k0);
            CPA16(ad + halfB, Ag + (size_t)64 * K + k0);
            CPA16(bd, Wg + k0);
            CPA16(bd + halfB, Wg + (size_t)64 * K + k0);
            asm volatile("cp.async.commit_group;\n");
            asm volatile("cp.async.wait_group 1;\n");
        } else {
            asm volatile("cp.async.wait_group 0;\n");
        }
        __syncthreads();

        const float* Asb = As[kt & 1];
        const float* Bsb = Bs[kt & 1];
        #pragma unroll
        for (int kk = 0; kk < 16; kk += 8) {
            uint32_t a[4][4], b[4][2];
            #pragma unroll
            for (int mt = 0; mt < 4; mt++) {
                int rb = wm * 64 + mt * 16;
                a[mt][0] = f2tf32(Asb[(rb + grp)     * LDS_ + kk + tig]);
                a[mt][1] = f2tf32(Asb[(rb + grp + 8) * LDS_ + kk + tig]);
                a[mt][2] = f2tf32(Asb[(rb + grp)     * LDS_ + kk + tig + 4]);
                a[mt][3] = f2tf32(Asb[(rb + grp + 8) * LDS_ + kk + tig + 4]);
            }
            #pragma unroll
            for (int nt = 0; nt < 4; nt++) {
                int cb = wn * 32 + nt * 8;
                b[nt][0] = f2tf32(Bsb[(cb + grp) * LDS_ + kk + tig]);
                b[nt][1] = f2tf32(Bsb[(cb + grp) * LDS_ + kk + tig + 4]);
            }
            #pragma unroll
            for (int mt = 0; mt < 4; mt++)
                #pragma unroll
                for (int nt = 0; nt < 4; nt++) {
                    asm volatile(
                        "mma.sync.aligned.m16n8k8.row.col.f32.tf32.tf32.f32 "
                        "{%0,%1,%2,%3}, {%4,%5,%6,%7}, {%8,%9}, {%0,%1,%2,%3};\n"
                        : "+f"(acc[mt][nt][0]), "+f"(acc[mt][nt][1]),
                          "+f"(acc[mt][nt][2]), "+f"(acc[mt][nt][3])
                        : "r"(a[mt][0]), "r"(a[mt][1]), "r"(a[mt][2]), "r"(a[mt][3]),
                          "r"(b[nt][0]), "r"(b[nt][1]));
                }
        }
        __syncthreads();
    }

    // epilogue: c0/c1 -> (row grp, cols 2tig,2tig+1), c2/c3 -> row grp+8
    #pragma unroll
    for (int mt = 0; mt < 4; mt++) {
        int r = m0 + wm * 64 + mt * 16 + grp;
        #pragma unroll
        for (int nt = 0; nt < 4; nt++) {
            int c = n0 + wn * 32 + nt * 8 + tig * 2;
            float2 bv = *(const float2*)(bias + c);
            #pragma unroll
            for (int half = 0; half < 2; half++) {
                int rr = r + half * 8;
                float2 o;
                o.x = acc[mt][nt][half * 2 + 0] + bv.x;
                o.y = acc[mt][nt][half * 2 + 1] + bv.y;
                if (RES) {
                    float2 rv = *(const float2*)(res + (size_t)rr * N + c);
                    o.x += rv.x; o.y += rv.y;
                }
                if (RELU) { o.x = fmaxf(o.x, 0.f); o.y = fmaxf(o.y, 0.f); }
                *(float2*)(C + (size_t)rr * N + c) = o;
            }
        }
    }
}

// ---------------- RoPE + layout [S,B,3D] -> Q/K/V [B*H, S, HD] ----------------
__global__ __launch_bounds__(256) void rope_kernel(
    const float* __restrict__ qkv, const float* __restrict__ sn,
    const float* __restrict__ cs,
    float* __restrict__ Q, float* __restrict__ K, float* __restrict__ V)
{
    int idx = blockIdx.x * 256 + threadIdx.x;
    int p = idx & 31;
    int s = (idx >> 5) & 2047;
    int h = (idx >> 16) & 15;
    int b = idx >> 20;
    size_t rb = ((size_t)s * BAT + b) * (3 * DM) + h * HDM + 2 * p;
    float2 q = *(const float2*)(qkv + rb);
    float2 k = *(const float2*)(qkv + rb + DM);
    float2 v = *(const float2*)(qkv + rb + 2 * DM);
    float sv = sn[s * 32 + p], cv = cs[s * 32 + p];
    float2 qo = make_float2(q.x * cv - q.y * sv, q.y * cv + q.x * sv);
    float2 ko = make_float2(k.x * cv - k.y * sv, k.y * cv + k.x * sv);
    size_t ob = ((size_t)(b * NH + h) * SEQ + s) * HDM + 2 * p;
    *(float2*)(Q + ob) = qo;
    *(float2*)(K + ob) = ko;
    *(float2*)(V + ob) = v;
}

// ---------------- Flash attention (fp32), unchanged this round ----------------
__global__ __launch_bounds__(256) void attn_kernel(
    const float* __restrict__ Q, const float* __restrict__ K,
    const float* __restrict__ V, float* __restrict__ Out)
{
    extern __shared__ float smem[];
    float* Qt = smem;
    float* Kt = smem + 4096;
    float* Vs = Kt + 64 * 68;
    int tid = threadIdx.x;
    int tx = tid & 15, ty = tid >> 4;
    int qb = blockIdx.x, bh = blockIdx.y;
    int b = bh >> 4, h = bh & 15;

    const float* Qp = Q + ((size_t)bh * SEQ + qb * 64) * HDM;
    #pragma unroll
    for (int i = 0; i < 4; i++) {
        int lin = tid + i * 256;
        int r = lin >> 4, c4 = (lin & 15) << 2;
        float4 v = *(const float4*)(Qp + r * 64 + c4);
        Qt[(c4 + 0) * 64 + r] = v.x;
        Qt[(c4 + 1) * 64 + r] = v.y;
        Qt[(c4 + 2) * 64 + r] = v.z;
        Qt[(c4 + 3) * 64 + r] = v.w;
    }

    float o[4][4];
    float m_i[4], l_i[4];
    #pragma unroll
    for (int qi = 0; qi < 4; qi++) {
        m_i[qi] = -1e30f; l_i[qi] = 0.f;
        #pragma unroll
        for (int di = 0; di < 4; di++) o[qi][di] = 0.f;
    }

    for (int kb = 0; kb <= qb; kb++) {
        const float* Kp = K + ((size_t)bh * SEQ + kb * 64) * HDM;
        const float* Vp = V + ((size_t)bh * SEQ + kb * 64) * HDM;
        __syncthreads();
        #pragma unroll
        for (int i = 0; i < 4; i++) {
            int lin = tid + i * 256;
            int r = lin >> 4, c4 = (lin & 15) << 2;
            float4 kv = *(const float4*)(Kp + r * 64 + c4);
            Kt[(c4 + 0) * 68 + r] = kv.x;
            Kt[(c4 + 1) * 68 + r] = kv.y;
            Kt[(c4 + 2) * 68 + r] = kv.z;
            Kt[(c4 + 3) * 68 + r] = kv.w;
            float4 vv = *(const float4*)(Vp + r * 64 + c4);
            *(float4*)(Vs + r * 64 + c4) = vv;
        }
        __syncthreads();

        float s[4][4];
        #pragma unroll
        for (int qi = 0; qi < 4; qi++)
            #pragma unroll
            for (int ki = 0; ki < 4; ki++) s[qi][ki] = 0.f;

        #pragma unroll 8
        for (int d = 0; d < 64; d++) {
            float aq[4], bk[4];
            *(float4*)aq = *(const float4*)(Qt + d * 64 + (ty << 2));
            *(float4*)bk = *(const float4*)(Kt + d * 68 + (tx << 2));
            #pragma unroll
            for (int qi = 0; qi < 4; qi++)
                #pragma unroll
                for (int ki = 0; ki < 4; ki++)
                    s[qi][ki] += aq[qi] * bk[ki];
        }

        bool diag = (kb == qb);
        #pragma unroll
        for (int qi = 0; qi < 4; qi++)
            #pragma unroll
            for (int ki = 0; ki < 4; ki++) {
                s[qi][ki] *= 0.125f;
                if (diag && ((tx << 2) + ki) > ((ty << 2) + qi)) s[qi][ki] = -1e30f;
            }

        #pragma unroll
        for (int qi = 0; qi < 4; qi++) {
            float mx = fmaxf(fmaxf(s[qi][0], s[qi][1]), fmaxf(s[qi][2], s[qi][3]));
            mx = fmaxf(mx, __shfl_xor_sync(0xffffffffu, mx, 1));
            mx = fmaxf(mx, __shfl_xor_sync(0xffffffffu, mx, 2));
            mx = fmaxf(mx, __shfl_xor_sync(0xffffffffu, mx, 4));
            mx = fmaxf(mx, __shfl_xor_sync(0xffffffffu, mx, 8));
            float mn = fmaxf(m_i[qi], mx);
            float al = __expf(m_i[qi] - mn);
            float rs = 0.f;
            #pragma unroll
            for (int ki = 0; ki < 4; ki++) {
                s[qi][ki] = __expf(s[qi][ki] - mn);
                rs += s[qi][ki];
            }
            rs += __shfl_xor_sync(0xffffffffu, rs, 1);
            rs += __shfl_xor_sync(0xffffffffu, rs, 2);
            rs += __shfl_xor_sync(0xffffffffu, rs, 4);
            rs += __shfl_xor_sync(0xffffffffu, rs, 8);
            l_i[qi] = l_i[qi] * al + rs;
            m_i[qi] = mn;
            #pragma unroll
            for (int di = 0; di < 4; di++) o[qi][di] *= al;
        }

        __syncthreads();
        #pragma unroll
        for (int ki = 0; ki < 4; ki++) {
            *(float4*)(Kt + ((tx << 2) + ki) * 68 + (ty << 2)) =
                make_float4(s[0][ki], s[1][ki], s[2][ki], s[3][ki]);
        }
        __syncthreads();

        #pragma unroll 8
        for (int k = 0; k < 64; k++) {
            float ap[4], bv[4];
            *(float4*)ap = *(const float4*)(Kt + k * 68 + (ty << 2));
            *(float4*)bv = *(const float4*)(Vs + k * 64 + (tx << 2));
            #pragma unroll
            for (int qi = 0; qi < 4; qi++)
                #pragma unroll
                for (int di = 0; di < 4; di++)
                    o[qi][di] += ap[qi] * bv[di];
        }
    }

    #pragma unroll
    for (int qi = 0; qi < 4; qi++) {
        float inv = 1.f / l_i[qi];
        int qg = qb * 64 + (ty << 2) + qi;
        float4 ov = make_float4(o[qi][0] * inv, o[qi][1] * inv,
                                o[qi][2] * inv, o[qi][3] * inv);
        *(float4*)(Out + ((size_t)qg * BAT + b) * DM + h * HDM + (tx << 2)) = ov;
    }
}

// ---------------- launcher ----------------
extern "C" void kernel_launch(void* const* d_in, const int* in_sizes, int n_in,
                              void* d_out, int out_size)
{
    const float* src  = (const float*)d_in[0];
    const float* sn   = (const float*)d_in[1];
    const float* cs   = (const float*)d_in[2];
    const float* wqkv = (const float*)d_in[3];
    const float* bqkv = (const float*)d_in[4];
    const float* wo   = (const float*)d_in[5];
    const float* bo   = (const float*)d_in[6];
    const float* g1   = (const float*)d_in[7];
    const float* be1  = (const float*)d_in[8];
    const float* g2   = (const float*)d_in[9];
    const float* be2  = (const float*)d_in[10];
    const float* w1   = (const float*)d_in[11];
    const float* bb1  = (const float*)d_in[12];
    const float* w2   = (const float*)d_in[13];
    const float* bb2  = (const float*)d_in[14];
    float* out = (float*)d_out;

    float *xln, *qkv, *q, *k, *v, *att, *x, *h1;
    cudaGetSymbolAddress((void**)&xln, g_xln);
    cudaGetSymbolAddress((void**)&qkv, g_qkv);
    cudaGetSymbolAddress((void**)&q,   g_q);
    cudaGetSymbolAddress((void**)&k,   g_k);
    cudaGetSymbolAddress((void**)&v,   g_v);
    cudaGetSymbolAddress((void**)&att, g_att);
    cudaGetSymbolAddress((void**)&x,   g_x);
    cudaGetSymbolAddress((void**)&h1,  g_h1);

    const int ATTN_SMEM = (4096 + 64 * 68 + 4096) * 4;
    cudaFuncSetAttribute(attn_kernel, cudaFuncAttributeMaxDynamicSharedMemorySize, ATTN_SMEM);

    // 1. LN1
    ln_kernel<<<ROWS, 256>>>(src, g1, be1, xln);
    // 2. QKV projection (tf32 TC)
    gemm_tc<false, false><<<dim3(3 * DM / 128, ROWS / 128), 256>>>(
        xln, wqkv, bqkv, nullptr, qkv, ROWS, 3 * DM, DM);
    // 3. RoPE + transpose
    rope_kernel<<<(BAT * NH * SEQ * 32) / 256, 256>>>(qkv, sn, cs, q, k, v);
    // 4. Causal flash attention
    attn_kernel<<<dim3(SEQ / 64, BAT * NH), 256, ATTN_SMEM>>>(q, k, v, att);
    // 5. out-proj + residual (tf32 TC)
    gemm_tc<false, true><<<dim3(DM / 128, ROWS / 128), 256>>>(
        att, wo, bo, src, x, ROWS, DM, DM);
    // 6. LN2
    ln_kernel<<<ROWS, 256>>>(x, g2, be2, xln);
    // 7. FFN up + ReLU (tf32 TC)
    gemm_tc<true, false><<<dim3(DFF / 128, ROWS / 128), 256>>>(
        xln, w1, bb1, nullptr, h1, ROWS, DFF, DM);
    // 8. FFN down + residual -> out (tf32 TC)
    gemm_tc<false, true><<<dim3(DM / 128, ROWS / 128), 256>>>(
        h1, w2, bb2, x, out, ROWS, DM, DFF);
}

// round 3
// speedup vs baseline: 3.1141x; 1.5007x over previous
#include <cuda_runtime.h>
#include <math.h>
#include <stdint.h>

#define SEQ  2048
#define BAT  2
#define DM   1024
#define NH   16
#define HDM  64
#define DFF  4096
#define ROWS (SEQ*BAT)   // 4096

// ---------------- scratch (static device globals; no allocation) ----------------
__device__ float g_xln[ROWS * DM];
__device__ float g_qkv[ROWS * 3 * DM];
__device__ float g_q[BAT * NH * SEQ * HDM];
__device__ float g_k[BAT * NH * SEQ * HDM];
__device__ float g_v[BAT * NH * SEQ * HDM];
__device__ float g_att[ROWS * DM];
__device__ float g_x[ROWS * DM];
__device__ float g_h1[ROWS * DFF];

__device__ __forceinline__ uint32_t f2tf32(float f) {
    uint32_t u;
    asm("cvt.rna.tf32.f32 %0, %1;" : "=r"(u) : "f"(f));
    return u;
}

// ---------------- LayerNorm ----------------
__global__ __launch_bounds__(256) void ln_kernel(
    const float* __restrict__ x, const float* __restrict__ g,
    const float* __restrict__ b, float* __restrict__ y)
{
    int row = blockIdx.x;
    int t = threadIdx.x;
    const float4* xr = (const float4*)(x + (size_t)row * DM);
    float4 v = xr[t];
    float s  = v.x + v.y + v.z + v.w;
    float ss = v.x*v.x + v.y*v.y + v.z*v.z + v.w*v.w;
    #pragma unroll
    for (int o = 16; o > 0; o >>= 1) {
        s  += __shfl_xor_sync(0xffffffffu, s,  o);
        ss += __shfl_xor_sync(0xffffffffu, ss, o);
    }
    __shared__ float red[18];
    if ((t & 31) == 0) { red[t >> 5] = s; red[(t >> 5) + 8] = ss; }
    __syncthreads();
    if (t == 0) {
        float S_ = 0.f, SS = 0.f;
        #pragma unroll
        for (int i = 0; i < 8; i++) { S_ += red[i]; SS += red[i + 8]; }
        float mu  = S_ * (1.f / DM);
        float var = SS * (1.f / DM) - mu * mu;
        red[16] = mu;
        red[17] = rsqrtf(var + 1e-5f);
    }
    __syncthreads();
    float mu = red[16], inv = red[17];
    float4 gg = ((const float4*)g)[t];
    float4 bb = ((const float4*)b)[t];
    float4 o;
    o.x = (v.x - mu) * inv * gg.x + bb.x;
    o.y = (v.y - mu) * inv * gg.y + bb.y;
    o.z = (v.z - mu) * inv * gg.z + bb.z;
    o.w = (v.w - mu) * inv * gg.w + bb.w;
    ((float4*)(y + (size_t)row * DM))[t] = o;
}

// ---------------- tf32 tensor-core GEMM (unchanged from R2) ----------------
#define CPA16(dst, src) \
    asm volatile("cp.async.cg.shared.global [%0], [%1], 16;\n" :: "r"(dst), "l"(src))

template<bool RELU, bool RES>
__global__ __launch_bounds__(256) void gemm_tc(
    const float* __restrict__ A, const float* __restrict__ W,
    const float* __restrict__ bias, const float* __restrict__ res,
    float* __restrict__ C, int M, int N, int K)
{
    const int LDS_ = 20;
    __shared__ float As[2][128 * 20];
    __shared__ float Bs[2][128 * 20];
    int tid = threadIdx.x;
    int warp = tid >> 5, lane = tid & 31;
    int wm = warp >> 2, wn = warp & 3;
    int grp = lane >> 2, tig = lane & 3;
    int m0 = blockIdx.y << 7, n0 = blockIdx.x << 7;

    int lrow = tid >> 2;
    int lcol = (tid & 3) << 2;
    const float* Ag = A + (size_t)(m0 + lrow) * K + lcol;
    const float* Wg = W + (size_t)(n0 + lrow) * K + lcol;
    uint32_t sA = (uint32_t)__cvta_generic_to_shared(&As[0][0]);
    uint32_t sB = (uint32_t)__cvta_generic_to_shared(&Bs[0][0]);
    uint32_t doff = (uint32_t)(lrow * LDS_ + lcol) * 4u;
    const uint32_t stageB = 128u * LDS_ * 4u;
    const uint32_t halfB  = 64u * LDS_ * 4u;

    float acc[4][4][4];
    #pragma unroll
    for (int mt = 0; mt < 4; mt++)
        #pragma unroll
        for (int nt = 0; nt < 4; nt++)
            #pragma unroll
            for (int i = 0; i < 4; i++) acc[mt][nt][i] = 0.f;

    int KT = K >> 4;
    {
        uint32_t ad = sA + doff, bd = sB + doff;
        CPA16(ad, Ag);
        CPA16(ad + halfB, Ag + (size_t)64 * K);
        CPA16(bd, Wg);
        CPA16(bd + halfB, Wg + (size_t)64 * K);
        asm volatile("cp.async.commit_group;\n");
    }

    for (int kt = 0; kt < KT; kt++) {
        if (kt + 1 < KT) {
            int k0 = (kt + 1) << 4;
            uint32_t st = ((kt + 1) & 1) * stageB;
            uint32_t ad = sA + st + doff, bd = sB + st + doff;
            CPA16(ad, Ag + k0);
            CPA16(ad + halfB, Ag + (size_t)64 * K + k0);
            CPA16(bd, Wg + k0);
            CPA16(bd + halfB, Wg + (size_t)64 * K + k0);
            asm volatile("cp.async.commit_group;\n");
            asm volatile("cp.async.wait_group 1;\n");
        } else {
            asm volatile("cp.async.wait_group 0;\n");
        }
        __syncthreads();

        const float* Asb = As[kt & 1];
        const float* Bsb = Bs[kt & 1];
        #pragma unroll
        for (int kk = 0; kk < 16; kk += 8) {
            uint32_t a[4][4], b[4][2];
            #pragma unroll
            for (int mt = 0; mt < 4; mt++) {
                int rb = wm * 64 + mt * 16;
                a[mt][0] = f2tf32(Asb[(rb + grp)     * LDS_ + kk + tig]);
                a[mt][1] = f2tf32(Asb[(rb + grp + 8) * LDS_ + kk + tig]);
                a[mt][2] = f2tf32(Asb[(rb + grp)     * LDS_ + kk + tig + 4]);
                a[mt][3] = f2tf32(Asb[(rb + grp + 8) * LDS_ + kk + tig + 4]);
            }
            #pragma unroll
            for (int nt = 0; nt < 4; nt++) {
                int cb = wn * 32 + nt * 8;
                b[nt][0] = f2tf32(Bsb[(cb + grp) * LDS_ + kk + tig]);
                b[nt][1] = f2tf32(Bsb[(cb + grp) * LDS_ + kk + tig + 4]);
            }
            #pragma unroll
            for (int mt = 0; mt < 4; mt++)
                #pragma unroll
                for (int nt = 0; nt < 4; nt++) {
                    asm volatile(
                        "mma.sync.aligned.m16n8k8.row.col.f32.tf32.tf32.f32 "
                        "{%0,%1,%2,%3}, {%4,%5,%6,%7}, {%8,%9}, {%0,%1,%2,%3};\n"
                        : "+f"(acc[mt][nt][0]), "+f"(acc[mt][nt][1]),
                          "+f"(acc[mt][nt][2]), "+f"(acc[mt][nt][3])
                        : "r"(a[mt][0]), "r"(a[mt][1]), "r"(a[mt][2]), "r"(a[mt][3]),
                          "r"(b[nt][0]), "r"(b[nt][1]));
                }
        }
        __syncthreads();
    }

    #pragma unroll
    for (int mt = 0; mt < 4; mt++) {
        int r = m0 + wm * 64 + mt * 16 + grp;
        #pragma unroll
        for (int nt = 0; nt < 4; nt++) {
            int c = n0 + wn * 32 + nt * 8 + tig * 2;
            float2 bv = *(const float2*)(bias + c);
            #pragma unroll
            for (int half = 0; half < 2; half++) {
                int rr = r + half * 8;
                float2 o;
                o.x = acc[mt][nt][half * 2 + 0] + bv.x;
                o.y = acc[mt][nt][half * 2 + 1] + bv.y;
                if (RES) {
                    float2 rv = *(const float2*)(res + (size_t)rr * N + c);
                    o.x += rv.x; o.y += rv.y;
                }
                if (RELU) { o.x = fmaxf(o.x, 0.f); o.y = fmaxf(o.y, 0.f); }
                *(float2*)(C + (size_t)rr * N + c) = o;
            }
        }
    }
}

// ---------------- RoPE + layout [S,B,3D] -> Q/K/V [B*H, S, HD] ----------------
__global__ __launch_bounds__(256) void rope_kernel(
    const float* __restrict__ qkv, const float* __restrict__ sn,
    const float* __restrict__ cs,
    float* __restrict__ Q, float* __restrict__ K, float* __restrict__ V)
{
    int idx = blockIdx.x * 256 + threadIdx.x;
    int p = idx & 31;
    int s = (idx >> 5) & 2047;
    int h = (idx >> 16) & 15;
    int b = idx >> 20;
    size_t rb = ((size_t)s * BAT + b) * (3 * DM) + h * HDM + 2 * p;
    float2 q = *(const float2*)(qkv + rb);
    float2 k = *(const float2*)(qkv + rb + DM);
    float2 v = *(const float2*)(qkv + rb + 2 * DM);
    float sv = sn[s * 32 + p], cv = cs[s * 32 + p];
    float2 qo = make_float2(q.x * cv - q.y * sv, q.y * cv + q.x * sv);
    float2 ko = make_float2(k.x * cv - k.y * sv, k.y * cv + k.x * sv);
    size_t ob = ((size_t)(b * NH + h) * SEQ + s) * HDM + 2 * p;
    *(float2*)(Q + ob) = qo;
    *(float2*)(K + ob) = ko;
    *(float2*)(V + ob) = v;
}

// ---------------- tf32 tensor-core flash attention ----------------
// 64-query tile, 128 threads = 4 warps, each warp owns 16 query rows.
// smem: K[64][68] tf32, V[64][72] tf32, QP[64][68] (Q, then reused as P).
#define KS_LD 68
#define VS_LD 72

__global__ __launch_bounds__(128) void attn_tc(
    const float* __restrict__ Q, const float* __restrict__ K,
    const float* __restrict__ V, float* __restrict__ Out)
{
    extern __shared__ float sm[];
    float* Ks = sm;                     // 64 x 68
    float* Vs = sm + 64 * KS_LD;        // 64 x 72
    float* Ps = Vs + 64 * VS_LD;        // 64 x 68 (Q staging, then P)
    int tid = threadIdx.x;
    int warp = tid >> 5, lane = tid & 31;
    int grp = lane >> 2, tig = lane & 3;
    int qb = blockIdx.x, bh = blockIdx.y;
    int b = bh >> 4, h = bh & 15;
    int rb = warp * 16;

    // load Q tile (scaled by 1/sqrt(HD)) into Ps
    const float* Qg = Q + ((size_t)bh * SEQ + qb * 64) * HDM;
    #pragma unroll
    for (int i = 0; i < 8; i++) {
        int idx = tid + i * 128;
        int r = idx >> 4, c = (idx & 15) << 2;
        float4 v = *(const float4*)(Qg + r * 64 + c);
        Ps[r * KS_LD + c + 0] = v.x * 0.125f;
        Ps[r * KS_LD + c + 1] = v.y * 0.125f;
        Ps[r * KS_LD + c + 2] = v.z * 0.125f;
        Ps[r * KS_LD + c + 3] = v.w * 0.125f;
    }
    __syncthreads();

    // preload Q fragments (tf32), then Ps becomes the P buffer
    uint32_t qa[8][4];
    #pragma unroll
    for (int kk = 0; kk < 8; kk++) {
        qa[kk][0] = f2tf32(Ps[(rb + grp)     * KS_LD + kk * 8 + tig]);
        qa[kk][1] = f2tf32(Ps[(rb + grp + 8) * KS_LD + kk * 8 + tig]);
        qa[kk][2] = f2tf32(Ps[(rb + grp)     * KS_LD + kk * 8 + tig + 4]);
        qa[kk][3] = f2tf32(Ps[(rb + grp + 8) * KS_LD + kk * 8 + tig + 4]);
    }

    float oacc[8][4];
    #pragma unroll
    for (int nt = 0; nt < 8; nt++)
        #pragma unroll
        for (int i = 0; i < 4; i++) oacc[nt][i] = 0.f;
    float m_i[2] = {-1e30f, -1e30f};
    float l_i[2] = {0.f, 0.f};

    for (int kb = 0; kb <= qb; kb++) {
        __syncthreads();   // previous iter's PV reads of Ks/Vs done
        const float* Kg = K + ((size_t)bh * SEQ + kb * 64) * HDM;
        const float* Vg = V + ((size_t)bh * SEQ + kb * 64) * HDM;
        #pragma unroll
        for (int i = 0; i < 8; i++) {
            int idx = tid + i * 128;
            int r = idx >> 4, c = (idx & 15) << 2;
            float4 kv = *(const float4*)(Kg + r * 64 + c);
            Ks[r * KS_LD + c + 0] = __uint_as_float(f2tf32(kv.x));
            Ks[r * KS_LD + c + 1] = __uint_as_float(f2tf32(kv.y));
            Ks[r * KS_LD + c + 2] = __uint_as_float(f2tf32(kv.z));
            Ks[r * KS_LD + c + 3] = __uint_as_float(f2tf32(kv.w));
            float4 vv = *(const float4*)(Vg + r * 64 + c);
            Vs[r * VS_LD + c + 0] = __uint_as_float(f2tf32(vv.x));
            Vs[r * VS_LD + c + 1] = __uint_as_float(f2tf32(vv.y));
            Vs[r * VS_LD + c + 2] = __uint_as_float(f2tf32(vv.z));
            Vs[r * VS_LD + c + 3] = __uint_as_float(f2tf32(vv.w));
        }
        __syncthreads();

        // S = Q @ K^T  (warp: 16 rows x 64 keys)
        float sacc[8][4];
        #pragma unroll
        for (int nt = 0; nt < 8; nt++)
            #pragma unroll
            for (int i = 0; i < 4; i++) sacc[nt][i] = 0.f;
        #pragma unroll
        for (int kk = 0; kk < 8; kk++) {
            #pragma unroll
            for (int nt = 0; nt < 8; nt++) {
                uint32_t b0 = __float_as_uint(Ks[(nt * 8 + grp) * KS_LD + kk * 8 + tig]);
                uint32_t b1 = __float_as_uint(Ks[(nt * 8 + grp) * KS_LD + kk * 8 + tig + 4]);
                asm volatile(
                    "mma.sync.aligned.m16n8k8.row.col.f32.tf32.tf32.f32 "
                    "{%0,%1,%2,%3}, {%4,%5,%6,%7}, {%8,%9}, {%0,%1,%2,%3};\n"
                    : "+f"(sacc[nt][0]), "+f"(sacc[nt][1]),
                      "+f"(sacc[nt][2]), "+f"(sacc[nt][3])
                    : "r"(qa[kk][0]), "r"(qa[kk][1]), "r"(qa[kk][2]), "r"(qa[kk][3]),
                      "r"(b0), "r"(b1));
            }
        }

        if (kb == qb) {   // causal mask on diagonal tile (local coords)
            #pragma unroll
            for (int nt = 0; nt < 8; nt++) {
                int c0 = nt * 8 + 2 * tig;
                int r0 = rb + grp;
                if (c0     > r0)     sacc[nt][0] = -1e30f;
                if (c0 + 1 > r0)     sacc[nt][1] = -1e30f;
                if (c0     > r0 + 8) sacc[nt][2] = -1e30f;
                if (c0 + 1 > r0 + 8) sacc[nt][3] = -1e30f;
            }
        }

        // online softmax, two row-halves (rows rb+grp, rb+grp+8)
        #pragma unroll
        for (int hf = 0; hf < 2; hf++) {
            float mx = -1e30f;
            #pragma unroll
            for (int nt = 0; nt < 8; nt++)
                mx = fmaxf(mx, fmaxf(sacc[nt][2 * hf], sacc[nt][2 * hf + 1]));
            mx = fmaxf(mx, __shfl_xor_sync(0xffffffffu, mx, 1));
            mx = fmaxf(mx, __shfl_xor_sync(0xffffffffu, mx, 2));
            float mn = fmaxf(m_i[hf], mx);
            float al = __expf(m_i[hf] - mn);
            float rs = 0.f;
            int prow = (rb + grp + 8 * hf) * KS_LD;
            #pragma unroll
            for (int nt = 0; nt < 8; nt++) {
                float p0 = __expf(sacc[nt][2 * hf]     - mn);
                float p1 = __expf(sacc[nt][2 * hf + 1] - mn);
                rs += p0 + p1;
                float2 st;
                st.x = __uint_as_float(f2tf32(p0));
                st.y = __uint_as_float(f2tf32(p1));
                *(float2*)(Ps + prow + nt * 8 + 2 * tig) = st;
                oacc[nt][2 * hf]     *= al;
                oacc[nt][2 * hf + 1] *= al;
            }
            rs += __shfl_xor_sync(0xffffffffu, rs, 1);
            rs += __shfl_xor_sync(0xffffffffu, rs, 2);
            l_i[hf] = l_i[hf] * al + rs;
            m_i[hf] = mn;
        }
        __syncwarp();   // P rows consumed only by this warp

        // O += P @ V
        #pragma unroll
        for (int kk = 0; kk < 8; kk++) {
            uint32_t a0 = __float_as_uint(Ps[(rb + grp)     * KS_LD + kk * 8 + tig]);
            uint32_t a1 = __float_as_uint(Ps[(rb + grp + 8) * KS_LD + kk * 8 + tig]);
            uint32_t a2 = __float_as_uint(Ps[(rb + grp)     * KS_LD + kk * 8 + tig + 4]);
            uint32_t a3 = __float_as_uint(Ps[(rb + grp + 8) * KS_LD + kk * 8 + tig + 4]);
            #pragma unroll
            for (int nt = 0; nt < 8; nt++) {
                uint32_t b0 = __float_as_uint(Vs[(kk * 8 + tig)     * VS_LD + nt * 8 + grp]);
                uint32_t b1 = __float_as_uint(Vs[(kk * 8 + tig + 4) * VS_LD + nt * 8 + grp]);
                asm volatile(
                    "mma.sync.aligned.m16n8k8.row.col.f32.tf32.tf32.f32 "
                    "{%0,%1,%2,%3}, {%4,%5,%6,%7}, {%8,%9}, {%0,%1,%2,%3};\n"
                    : "+f"(oacc[nt][0]), "+f"(oacc[nt][1]),
                      "+f"(oacc[nt][2]), "+f"(oacc[nt][3])
                    : "r"(a0), "r"(a1), "r"(a2), "r"(a3),
                      "r"(b0), "r"(b1));
            }
        }
    }

    // epilogue: Out[S,B,D]
    float inv0 = 1.f / l_i[0], inv1 = 1.f / l_i[1];
    int q0 = qb * 64 + rb + grp;
    #pragma unroll
    for (int nt = 0; nt < 8; nt++) {
        int d = h * HDM + nt * 8 + 2 * tig;
        float2 o0 = make_float2(oacc[nt][0] * inv0, oacc[nt][1] * inv0);
        float2 o1 = make_float2(oacc[nt][2] * inv1, oacc[nt][3] * inv1);
        *(float2*)(Out + ((size_t)q0 * BAT + b) * DM + d)       = o0;
        *(float2*)(Out + ((size_t)(q0 + 8) * BAT + b) * DM + d) = o1;
    }
}

// ---------------- launcher ----------------
extern "C" void kernel_launch(void* const* d_in, const int* in_sizes, int n_in,
                              void* d_out, int out_size)
{
    const float* src  = (const float*)d_in[0];
    const float* sn   = (const float*)d_in[1];
    const float* cs   = (const float*)d_in[2];
    const float* wqkv = (const float*)d_in[3];
    const float* bqkv = (const float*)d_in[4];
    const float* wo   = (const float*)d_in[5];
    const float* bo   = (const float*)d_in[6];
    const float* g1   = (const float*)d_in[7];
    const float* be1  = (const float*)d_in[8];
    const float* g2   = (const float*)d_in[9];
    const float* be2  = (const float*)d_in[10];
    const float* w1   = (const float*)d_in[11];
    const float* bb1  = (const float*)d_in[12];
    const float* w2   = (const float*)d_in[13];
    const float* bb2  = (const float*)d_in[14];
    float* out = (float*)d_out;

    float *xln, *qkv, *q, *k, *v, *att, *x, *h1;
    cudaGetSymbolAddress((void**)&xln, g_xln);
    cudaGetSymbolAddress((void**)&qkv, g_qkv);
    cudaGetSymbolAddress((void**)&q,   g_q);
    cudaGetSymbolAddress((void**)&k,   g_k);
    cudaGetSymbolAddress((void**)&v,   g_v);
    cudaGetSymbolAddress((void**)&att, g_att);
    cudaGetSymbolAddress((void**)&x,   g_x);
    cudaGetSymbolAddress((void**)&h1,  g_h1);

    const int ATTN_SMEM = (64 * KS_LD + 64 * VS_LD + 64 * KS_LD) * 4;  // 53248
    cudaFuncSetAttribute(attn_tc, cudaFuncAttributeMaxDynamicSharedMemorySize, ATTN_SMEM);

    ln_kernel<<<ROWS, 256>>>(src, g1, be1, xln);
    gemm_tc<false, false><<<dim3(3 * DM / 128, ROWS / 128), 256>>>(
        xln, wqkv, bqkv, nullptr, qkv, ROWS, 3 * DM, DM);
    rope_kernel<<<(BAT * NH * SEQ * 32) / 256, 256>>>(qkv, sn, cs, q, k, v);
    attn_tc<<<dim3(SEQ / 64, BAT * NH), 128, ATTN_SMEM>>>(q, k, v, att);
    gemm_tc<false, true><<<dim3(DM / 128, ROWS / 128), 256>>>(
        att, wo, bo, src, x, ROWS, DM, DM);
    ln_kernel<<<ROWS, 256>>>(x, g2, be2, xln);
    gemm_tc<true, false><<<dim3(DFF / 128, ROWS / 128), 256>>>(
        xln, w1, bb1, nullptr, h1, ROWS, DFF, DM);
    gemm_tc<false, true><<<dim3(DM / 128, ROWS / 128), 256>>>(
        h1, w2, bb2, x, out, ROWS, DM, DFF);
}